// round 3
// baseline (speedup 1.0000x reference)
#include <cuda_runtime.h>
#include <cuda_fp16.h>

// ---------------------------------------------------------------------------
// fp32 chain for levels 1..7 (downsample sources, keeps accuracy).
// Texels per plane (levels 1..7): 256^2+128^2+64^2+32^2+16^2+8^2+4^2 = 87376.
// ---------------------------------------------------------------------------
#define PYR_PLANE_TEXELS 87376
#define PYR_PLANE_F4     (PYR_PLANE_TEXELS * 4)
__device__ float4 g_pyr[3 * PYR_PLANE_F4];          // 16.8 MB

// fp16 sampling pyramid for levels 0..7.
// Texels per plane: 262144 + 87376 = 349520. 16 channels each.
#define T_ALL 349520
__device__ __half g_pyrh[3 * T_ALL * 16];           // 33.6 MB

// Texel offsets within a plane.
__constant__ int c_off[8]   = {0, 0, 65536, 81920, 86016, 87040, 87296, 87360};       // fp32 chain (levels 1..7)
__constant__ int c_offa[8]  = {0, 262144, 327680, 344064, 348160, 349184, 349440, 349504}; // fp16 pyramid (levels 0..7)

// ---------------------------------------------------------------------------
// helpers
// ---------------------------------------------------------------------------
__device__ __forceinline__ void st_h4(__half* p, float4 v) {
    __half2 a = __floats2half2_rn(v.x, v.y);
    __half2 b = __floats2half2_rn(v.z, v.w);
    uint2 u;
    u.x = *reinterpret_cast<unsigned*>(&a);
    u.y = *reinterpret_cast<unsigned*>(&b);
    *reinterpret_cast<uint2*>(p) = u;
}

// ---------------------------------------------------------------------------
// Level 0 (fm fp32) -> fp16 level 0 copy + level 1 (fp32 + fp16).
// One thread per (plane, y, x, c4) of level-1 output.
// ---------------------------------------------------------------------------
__global__ void ds1_kernel(const float4* __restrict__ fm) {
    int idx = blockIdx.x * blockDim.x + threadIdx.x;
    if (idx >= 3 * 256 * 256 * 4) return;
    const int c4 = idx & 3;
    int t = idx >> 2;
    const int x = t & 255;
    const int y = (t >> 8) & 255;
    const int plane = t >> 16;

    const float4* src = fm + plane * (512 * 512 * 4);
    const int xi = x << 1, yi = y << 1;
    const float4 a = __ldg(src + (yi * 512 + xi) * 4 + c4);
    const float4 b = __ldg(src + (yi * 512 + xi + 1) * 4 + c4);
    const float4 c = __ldg(src + ((yi + 1) * 512 + xi) * 4 + c4);
    const float4 d = __ldg(src + ((yi + 1) * 512 + xi + 1) * 4 + c4);

    // fp16 level-0 copies of the 4 source texels
    __half* h0 = g_pyrh + ((size_t)plane * T_ALL) * 16 + c4 * 4;
    st_h4(h0 + (size_t)(yi * 512 + xi) * 16, a);
    st_h4(h0 + (size_t)(yi * 512 + xi + 1) * 16, b);
    st_h4(h0 + (size_t)((yi + 1) * 512 + xi) * 16, c);
    st_h4(h0 + (size_t)((yi + 1) * 512 + xi + 1) * 16, d);

    float4 r;
    r.x = (a.x + b.x + c.x + d.x) * 0.25f;
    r.y = (a.y + b.y + c.y + d.y) * 0.25f;
    r.z = (a.z + b.z + c.z + d.z) * 0.25f;
    r.w = (a.w + b.w + c.w + d.w) * 0.25f;

    const int tex = y * 256 + x;
    g_pyr[plane * PYR_PLANE_F4 + tex * 4 + c4] = r;
    st_h4(g_pyrh + ((size_t)plane * T_ALL + c_offa[1] + tex) * 16 + c4 * 4, r);
}

// ---------------------------------------------------------------------------
// Levels d0..d0+2 computed directly from fp32 level src_l via box average.
// ---------------------------------------------------------------------------
__global__ void ds_rest_kernel(int src_l, int d0) {
    int idx = blockIdx.x * blockDim.x + threadIdx.x;

    int lev = d0, rem = idx;
    #pragma unroll
    for (int i = 0; i < 3; ++i) {
        int sz = 512 >> (d0 + i);
        int n = 3 * sz * sz * 4;
        if (rem < n) { lev = d0 + i; break; }
        rem -= n;
        if (i == 2) return;
    }
    {
        int sz = 512 >> lev;
        int n = 3 * sz * sz * 4;
        if (lev == d0 + 2 && rem >= n) return;
    }

    const int c4 = rem & 3;
    int t = rem >> 2;
    const int shift = 9 - lev;
    const int s = 512 >> lev;
    const int x = t & (s - 1);
    const int y = (t >> shift) & (s - 1);
    const int plane = t >> (2 * shift);

    const int r = 1 << (lev - src_l);
    const int S = 512 >> src_l;
    const float4* src = g_pyr + plane * PYR_PLANE_F4 + c_off[src_l] * 4;

    float4 acc = make_float4(0.f, 0.f, 0.f, 0.f);
    const int xi = x * r, yi = y * r;
    for (int dy = 0; dy < r; ++dy)
        for (int dx = 0; dx < r; ++dx) {
            float4 v = __ldg(src + ((yi + dy) * S + xi + dx) * 4 + c4);
            acc.x += v.x; acc.y += v.y; acc.z += v.z; acc.w += v.w;
        }
    const float inv = 1.0f / (float)(r * r);
    acc.x *= inv; acc.y *= inv; acc.z *= inv; acc.w *= inv;

    g_pyr[plane * PYR_PLANE_F4 + (c_off[lev] + y * s + x) * 4 + c4] = acc;
    st_h4(g_pyrh + ((size_t)plane * T_ALL + c_offa[lev] + y * s + x) * 16 + c4 * 4, acc);
}

// ---------------------------------------------------------------------------
// Sampling
// ---------------------------------------------------------------------------
struct Corners {
    int i00, i01, i10, i11;       // texel indices
    float w00, w01, w10, w11;
};

__device__ __forceinline__ Corners corners(float u, float v, int size) {
    Corners c;
    const float fs = (float)size;
    const float px = u * fs - 0.5f;
    const float py = v * fs - 0.5f;
    const float x0f = floorf(px);
    const float y0f = floorf(py);
    const float fx = px - x0f;
    const float fy = py - y0f;
    const int x0 = (int)x0f;
    const int y0 = (int)y0f;
    const int sm1 = size - 1;
    const int xa = min(max(x0, 0), sm1);
    const int xb = min(max(x0 + 1, 0), sm1);
    const int ya = min(max(y0, 0), sm1);
    const int yb = min(max(y0 + 1, 0), sm1);
    c.i00 = ya * size + xa;
    c.i01 = ya * size + xb;
    c.i10 = yb * size + xa;
    c.i11 = yb * size + xb;
    c.w00 = (1.f - fx) * (1.f - fy);
    c.w01 = fx * (1.f - fy);
    c.w10 = (1.f - fx) * fy;
    c.w11 = fx * fy;
    return c;
}

// fma 8 fp16 channels (one uint4) into two float4 accumulators with weight w.
__device__ __forceinline__ void fma8(uint4 r, float w, float4& A, float4& B) {
    __half2 h0 = *reinterpret_cast<__half2*>(&r.x);
    __half2 h1 = *reinterpret_cast<__half2*>(&r.y);
    __half2 h2 = *reinterpret_cast<__half2*>(&r.z);
    __half2 h3 = *reinterpret_cast<__half2*>(&r.w);
    float2 f0 = __half22float2(h0);
    float2 f1 = __half22float2(h1);
    float2 f2 = __half22float2(h2);
    float2 f3 = __half22float2(h3);
    A.x = fmaf(w, f0.x, A.x); A.y = fmaf(w, f0.y, A.y);
    A.z = fmaf(w, f1.x, A.z); A.w = fmaf(w, f1.y, A.w);
    B.x = fmaf(w, f2.x, B.x); B.y = fmaf(w, f2.y, B.y);
    B.z = fmaf(w, f3.x, B.z); B.w = fmaf(w, f3.y, B.w);
}

// Accumulate one bilinear tap (8 channels selected by c2) scaled by mip weight mw.
__device__ __forceinline__ void bilin8(int plane, int li, float u, float v,
                                       int c2, float mw, float4& A, float4& B) {
    const int size = 512 >> li;
    const uint4* base = reinterpret_cast<const uint4*>(g_pyrh)
                        + ((size_t)plane * T_ALL + c_offa[li]) * 2 + c2;
    Corners c = corners(u, v, size);
    uint4 r00 = __ldg(base + c.i00 * 2);
    uint4 r01 = __ldg(base + c.i01 * 2);
    uint4 r10 = __ldg(base + c.i10 * 2);
    uint4 r11 = __ldg(base + c.i11 * 2);
    fma8(r00, mw * c.w00, A, B);
    fma8(r01, mw * c.w01, A, B);
    fma8(r10, mw * c.w10, A, B);
    fma8(r11, mw * c.w11, A, B);
}

// One thread per (point, plane, channel-half). c2 fastest.
__global__ void sample_kernel(const float* __restrict__ xin,
                              const float* __restrict__ level,
                              float4* __restrict__ out, int N) {
    int idx = blockIdx.x * blockDim.x + threadIdx.x;
    if (idx >= N * 6) return;

    const int c2 = idx & 1;
    int t = idx >> 1;
    const int plane = t % 3;
    const int pt = t / 3;

    const float xv = __ldg(xin + pt * 3 + 0);
    const float yv = __ldg(xin + pt * 3 + 1);
    const float zv = __ldg(xin + pt * 3 + 2);

    float u, v;
    if (plane == 0)      { u = yv; v = zv; }
    else if (plane == 1) { u = xv; v = zv; }
    else                 { u = xv; v = yv; }

    float lvl = __ldg(level + pt);
    lvl = fminf(fmaxf(lvl, 0.f), 7.f);
    const float l0f = floorf(lvl);
    const float f = lvl - l0f;
    const int l0 = (int)l0f;
    const int l1 = min(l0 + 1, 7);

    float4 A = make_float4(0.f, 0.f, 0.f, 0.f);
    float4 B = make_float4(0.f, 0.f, 0.f, 0.f);
    bilin8(plane, l0, u, v, c2, 1.f - f, A, B);
    bilin8(plane, l1, u, v, c2, f, A, B);

    float4* o = out + pt * 12 + plane * 4 + c2 * 2;
    o[0] = A;
    o[1] = B;
}

extern "C" void kernel_launch(void* const* d_in, const int* in_sizes, int n_in,
                              void* d_out, int out_size) {
    const float*  x     = (const float*)d_in[0];
    const float*  level = (const float*)d_in[1];
    const float4* fm    = (const float4*)d_in[2];
    float4* out = (float4*)d_out;
    const int N = in_sizes[0] / 3;

    const int threads = 256;

    {   // level 0 fp16 copy + level 1
        int total = 3 * 256 * 256 * 4;
        ds1_kernel<<<(total + threads - 1) / threads, threads>>>(fm);
    }
    {   // levels 2,3,4 from level 1
        int total = 3 * 4 * (128 * 128 + 64 * 64 + 32 * 32);
        ds_rest_kernel<<<(total + threads - 1) / threads, threads>>>(1, 2);
    }
    {   // levels 5,6,7 from level 4
        int total = 3 * 4 * (16 * 16 + 8 * 8 + 4 * 4);
        ds_rest_kernel<<<(total + threads - 1) / threads, threads>>>(4, 5);
    }
    {   // sample
        int total = N * 6;
        sample_kernel<<<(total + threads - 1) / threads, threads>>>(x, level, out, N);
    }
}

// round 4
// speedup vs baseline: 1.2914x; 1.2914x over previous
#include <cuda_runtime.h>
#include <cuda_fp16.h>

// fp16 sampling pyramid, levels 0..7 per plane.
// Texels/plane: 512^2+256^2+128^2+64^2+32^2+16^2+8^2+4^2 = 349520
#define T_ALL 349520
__device__ __half g_pyrh[3 * T_ALL * 16];     // 33.6 MB
__device__ float4 g_l5[3 * 256 * 4];          // fp32 level 5 (16x16), c4-sliced

__constant__ int c_offa[8] = {0, 262144, 327680, 344064, 348160, 349184, 349440, 349504};

__device__ __forceinline__ void st_h4(__half* p, float4 v) {
    __half2 a = __floats2half2_rn(v.x, v.y);
    __half2 b = __floats2half2_rn(v.z, v.w);
    uint2 u;
    u.x = *reinterpret_cast<unsigned*>(&a);
    u.y = *reinterpret_cast<unsigned*>(&b);
    *reinterpret_cast<uint2*>(p) = u;
}

__device__ __forceinline__ float4 avg4(float4 a, float4 b, float4 c, float4 d) {
    float4 r;
    r.x = (a.x + b.x + c.x + d.x) * 0.25f;
    r.y = (a.y + b.y + c.y + d.y) * 0.25f;
    r.z = (a.z + b.z + c.z + d.z) * 0.25f;
    r.w = (a.w + b.w + c.w + d.w) * 0.25f;
    return r;
}

// ---------------------------------------------------------------------------
// Fused downsample: block = (plane, 16x16 tile of 32x32 fm texels, c4 slice).
// Loads the fm tile once, writes fp16 L0, cascades L1..L5 in shared memory.
// ---------------------------------------------------------------------------
__global__ void ds_fused(const float4* __restrict__ fm) {
    __shared__ float4 s0[1024];   // 32x32
    __shared__ float4 s1[256];    // 16x16
    __shared__ float4 s2[64];     // 8x8
    __shared__ float4 s3[16];     // 4x4
    __shared__ float4 s4[4];      // 2x2

    const int b = blockIdx.x;
    const int c4 = b & 3;
    const int tile = (b >> 2) & 255;
    const int plane = b >> 10;
    const int tx = tile & 15, ty = tile >> 4;
    const int tid = threadIdx.x;

    const float4* src = fm + (size_t)plane * (512 * 512 * 4);
    __half* hp = g_pyrh + (size_t)plane * T_ALL * 16;

    // Load 32x32 region (level 0) + write fp16 L0 copy
    #pragma unroll
    for (int i = 0; i < 4; ++i) {
        int li = i * 256 + tid;
        int r = li >> 5, c = li & 31;
        int gy = ty * 32 + r, gx = tx * 32 + c;
        float4 v = __ldg(src + (gy * 512 + gx) * 4 + c4);
        s0[li] = v;
        st_h4(hp + (size_t)(gy * 512 + gx) * 16 + c4 * 4, v);
    }
    __syncthreads();

    // L1: 16x16
    {
        int r = tid >> 4, c = tid & 15;
        float4 v = avg4(s0[(2 * r) * 32 + 2 * c], s0[(2 * r) * 32 + 2 * c + 1],
                        s0[(2 * r + 1) * 32 + 2 * c], s0[(2 * r + 1) * 32 + 2 * c + 1]);
        s1[tid] = v;
        st_h4(hp + (size_t)(c_offa[1] + (ty * 16 + r) * 256 + tx * 16 + c) * 16 + c4 * 4, v);
    }
    __syncthreads();

    // L2: 8x8
    if (tid < 64) {
        int r = tid >> 3, c = tid & 7;
        float4 v = avg4(s1[(2 * r) * 16 + 2 * c], s1[(2 * r) * 16 + 2 * c + 1],
                        s1[(2 * r + 1) * 16 + 2 * c], s1[(2 * r + 1) * 16 + 2 * c + 1]);
        s2[tid] = v;
        st_h4(hp + (size_t)(c_offa[2] + (ty * 8 + r) * 128 + tx * 8 + c) * 16 + c4 * 4, v);
    }
    __syncthreads();

    // L3: 4x4
    if (tid < 16) {
        int r = tid >> 2, c = tid & 3;
        float4 v = avg4(s2[(2 * r) * 8 + 2 * c], s2[(2 * r) * 8 + 2 * c + 1],
                        s2[(2 * r + 1) * 8 + 2 * c], s2[(2 * r + 1) * 8 + 2 * c + 1]);
        s3[tid] = v;
        st_h4(hp + (size_t)(c_offa[3] + (ty * 4 + r) * 64 + tx * 4 + c) * 16 + c4 * 4, v);
    }
    __syncthreads();

    // L4: 2x2
    if (tid < 4) {
        int r = tid >> 1, c = tid & 1;
        float4 v = avg4(s3[(2 * r) * 4 + 2 * c], s3[(2 * r) * 4 + 2 * c + 1],
                        s3[(2 * r + 1) * 4 + 2 * c], s3[(2 * r + 1) * 4 + 2 * c + 1]);
        s4[tid] = v;
        st_h4(hp + (size_t)(c_offa[4] + (ty * 2 + r) * 32 + tx * 2 + c) * 16 + c4 * 4, v);
    }
    __syncthreads();

    // L5: 1 texel per block
    if (tid == 0) {
        float4 v = avg4(s4[0], s4[1], s4[2], s4[3]);
        st_h4(hp + (size_t)(c_offa[5] + ty * 16 + tx) * 16 + c4 * 4, v);
        g_l5[(plane * 256 + ty * 16 + tx) * 4 + c4] = v;
    }
}

// ---------------------------------------------------------------------------
// Levels 6 and 7 from fp32 level 5. Single block.
// ---------------------------------------------------------------------------
__global__ void ds_tail() {
    const int tid = threadIdx.x;
    if (tid < 768) {                                // level 6: 3 planes * 64 texels * 4 c4
        int c4 = tid & 3;
        int j = tid >> 2;
        int tex = j & 63;
        int plane = j >> 6;
        int r = tex >> 3, c = tex & 7;
        const float4* L5 = g_l5 + (size_t)plane * 256 * 4;
        float4 v = avg4(L5[((2 * r) * 16 + 2 * c) * 4 + c4],
                        L5[((2 * r) * 16 + 2 * c + 1) * 4 + c4],
                        L5[((2 * r + 1) * 16 + 2 * c) * 4 + c4],
                        L5[((2 * r + 1) * 16 + 2 * c + 1) * 4 + c4]);
        st_h4(g_pyrh + ((size_t)plane * T_ALL + c_offa[6] + r * 8 + c) * 16 + c4 * 4, v);
    } else if (tid < 960) {                         // level 7: 3 * 16 * 4, 4x4 box of L5
        int k = tid - 768;
        int c4 = k & 3;
        int j = k >> 2;
        int tex = j & 15;
        int plane = j >> 4;
        int r = tex >> 2, c = tex & 3;
        const float4* L5 = g_l5 + (size_t)plane * 256 * 4;
        float4 acc = make_float4(0.f, 0.f, 0.f, 0.f);
        #pragma unroll
        for (int dy = 0; dy < 4; ++dy)
            #pragma unroll
            for (int dx = 0; dx < 4; ++dx) {
                float4 t = L5[((4 * r + dy) * 16 + 4 * c + dx) * 4 + c4];
                acc.x += t.x; acc.y += t.y; acc.z += t.z; acc.w += t.w;
            }
        float4 v = make_float4(acc.x * 0.0625f, acc.y * 0.0625f,
                               acc.z * 0.0625f, acc.w * 0.0625f);
        st_h4(g_pyrh + ((size_t)plane * T_ALL + c_offa[7] + r * 4 + c) * 16 + c4 * 4, v);
    }
}

// ---------------------------------------------------------------------------
// Sample: 4 lanes per (point, plane): lane = (cx, c2).
// The 4 lanes' loads cover one contiguous 64B corner-row per instruction
// -> expected 1.25 L1 lines per row instead of 2.
// ---------------------------------------------------------------------------
__global__ void sample_kernel(const float* __restrict__ xin,
                              const float* __restrict__ level,
                              float4* __restrict__ out, int N3) {
    const int gid = blockIdx.x * blockDim.x + threadIdx.x;
    const int ps = gid >> 2;
    if (ps >= N3) return;
    const int sub = gid & 3;
    const int c2 = sub & 1;
    const int cx = sub >> 1;
    const int pt = ps / 3;
    const int plane = ps - pt * 3;

    const float xv = __ldg(xin + pt * 3 + 0);
    const float yv = __ldg(xin + pt * 3 + 1);
    const float zv = __ldg(xin + pt * 3 + 2);
    const float u = (plane == 0) ? yv : xv;
    const float v = (plane == 2) ? yv : zv;

    float lvl = fminf(fmaxf(__ldg(level + pt), 0.f), 7.f);
    const float l0f = floorf(lvl);
    const float f = lvl - l0f;
    const int l0 = (int)l0f;
    const int l1 = min(l0 + 1, 7);

    const uint4* pyr = reinterpret_cast<const uint4*>(g_pyrh) + (size_t)plane * T_ALL * 2;

    float4 A = make_float4(0.f, 0.f, 0.f, 0.f);   // channels [c2*8 .. +4)
    float4 B = make_float4(0.f, 0.f, 0.f, 0.f);   // channels [c2*8+4 .. +8)

    int   li = l0;
    float wm = 1.f - f;
    #pragma unroll
    for (int it = 0; it < 2; ++it) {
        const int size = 512 >> li;
        const float fs = (float)size;
        const float px = u * fs - 0.5f;
        const float py = v * fs - 0.5f;
        const float x0f = floorf(px);
        const float y0f = floorf(py);
        const float fx = px - x0f;
        const float fy = py - y0f;
        const int x0 = (int)x0f;
        const int y0 = (int)y0f;
        const int sm1 = size - 1;
        const int xa = min(max(x0, 0), sm1);
        const int xb = min(max(x0 + 1, 0), sm1);
        const int ya = min(max(y0, 0), sm1);
        const int yb = min(max(y0 + 1, 0), sm1);

        const int xc = cx ? xb : xa;
        const float wx = cx ? fx : (1.f - fx);

        const uint4* bl = pyr + c_offa[li] * 2;
        const uint4 ra = __ldg(bl + (ya * size + xc) * 2 + c2);
        const uint4 rb = __ldg(bl + (yb * size + xc) * 2 + c2);

        // fp16 row combine: h = ra*(1-fy) + rb*fy
        const __half2 wya = __float2half2_rn(1.f - fy);
        const __half2 wyb = __float2half2_rn(fy);
        const __half2 h0 = __hfma2(*(const __half2*)&rb.x, wyb, __hmul2(*(const __half2*)&ra.x, wya));
        const __half2 h1 = __hfma2(*(const __half2*)&rb.y, wyb, __hmul2(*(const __half2*)&ra.y, wya));
        const __half2 h2 = __hfma2(*(const __half2*)&rb.z, wyb, __hmul2(*(const __half2*)&ra.z, wya));
        const __half2 h3 = __hfma2(*(const __half2*)&rb.w, wyb, __hmul2(*(const __half2*)&ra.w, wya));

        const float wl = wx * wm;
        const float2 f0 = __half22float2(h0);
        const float2 f1 = __half22float2(h1);
        const float2 f2 = __half22float2(h2);
        const float2 f3 = __half22float2(h3);
        A.x = fmaf(wl, f0.x, A.x); A.y = fmaf(wl, f0.y, A.y);
        A.z = fmaf(wl, f1.x, A.z); A.w = fmaf(wl, f1.y, A.w);
        B.x = fmaf(wl, f2.x, B.x); B.y = fmaf(wl, f2.y, B.y);
        B.z = fmaf(wl, f3.x, B.z); B.w = fmaf(wl, f3.y, B.w);

        li = l1;
        wm = f;
    }

    // reduce over cx (xor lane mask 2)
    const unsigned m = 0xFFFFFFFFu;
    A.x += __shfl_xor_sync(m, A.x, 2);
    A.y += __shfl_xor_sync(m, A.y, 2);
    A.z += __shfl_xor_sync(m, A.z, 2);
    A.w += __shfl_xor_sync(m, A.w, 2);
    B.x += __shfl_xor_sync(m, B.x, 2);
    B.y += __shfl_xor_sync(m, B.y, 2);
    B.z += __shfl_xor_sync(m, B.z, 2);
    B.w += __shfl_xor_sync(m, B.w, 2);

    // lane (c2, cx) writes channel slice c2*8 + cx*4 .. +4
    const float4 o = cx ? B : A;
    out[ps * 4 + c2 * 2 + cx] = o;
}

extern "C" void kernel_launch(void* const* d_in, const int* in_sizes, int n_in,
                              void* d_out, int out_size) {
    const float*  x     = (const float*)d_in[0];
    const float*  level = (const float*)d_in[1];
    const float4* fm    = (const float4*)d_in[2];
    float4* out = (float4*)d_out;
    const int N = in_sizes[0] / 3;
    const int N3 = N * 3;

    ds_fused<<<3072, 256>>>(fm);
    ds_tail<<<1, 1024>>>();

    const int total = N3 * 4;
    const int threads = 256;
    sample_kernel<<<(total + threads - 1) / threads, threads>>>(x, level, out, N3);
}

// round 5
// speedup vs baseline: 1.4845x; 1.1495x over previous
#include <cuda_runtime.h>
#include <cuda_fp16.h>

// fp16 pyramid, levels 1..7 only. Texels/plane: 256^2+128^2+64^2+32^2+16^2+8^2+4^2 = 87376.
#define PLT 87376
__device__ __half g_pyrh[3 * PLT * 16];     // 8.4 MB
__device__ float4 g_l4[3 * 1024 * 4];       // fp32 level 4 (32x32 per plane), c4-sliced

// texel offset of level l (1..7) within a plane's fp16 region
__constant__ int c_off[8] = {0, 0, 65536, 81920, 86016, 87040, 87296, 87360};

__device__ __forceinline__ void st_h4(__half* p, float4 v) {
    __half2 a = __floats2half2_rn(v.x, v.y);
    __half2 b = __floats2half2_rn(v.z, v.w);
    uint2 u;
    u.x = *reinterpret_cast<unsigned*>(&a);
    u.y = *reinterpret_cast<unsigned*>(&b);
    *reinterpret_cast<uint2*>(p) = u;
}

__device__ __forceinline__ float4 avg4(float4 a, float4 b, float4 c, float4 d) {
    float4 r;
    r.x = (a.x + b.x + c.x + d.x) * 0.25f;
    r.y = (a.y + b.y + c.y + d.y) * 0.25f;
    r.z = (a.z + b.z + c.z + d.z) * 0.25f;
    r.w = (a.w + b.w + c.w + d.w) * 0.25f;
    return r;
}

// ---------------------------------------------------------------------------
// ds_fused: block = (plane, 16x16 L0 tile). Fully-coalesced fm load into smem,
// cascade L1..L4 in smem, coalesced fp16 stores. No fp16 L0 copy.
// grid = 3 * 1024 blocks, 256 threads.
// ---------------------------------------------------------------------------
__global__ void ds_fused(const float4* __restrict__ fm) {
    __shared__ float4 s0[1024];   // 16x16 texels x 4 f4
    __shared__ float4 s1[256];    // 8x8
    __shared__ float4 s2[64];     // 4x4
    __shared__ float4 s3[16];     // 2x2

    const int b = blockIdx.x;
    const int tile = b & 1023;
    const int plane = b >> 10;
    const int tx = tile & 31, ty = tile >> 5;
    const int tid = threadIdx.x;

    const float4* src = fm + (size_t)plane * (512 * 512 * 4);
    __half* hp = g_pyrh + (size_t)plane * PLT * 16;

    // Load 16x16x4 = 1024 float4, 4 per thread, 1KB-contiguous per tile row.
    #pragma unroll
    for (int i = 0; i < 4; ++i) {
        int idx = i * 256 + tid;
        int r = idx >> 6, o = idx & 63;
        s0[idx] = __ldg(src + (size_t)(ty * 16 + r) * 2048 + tx * 64 + o);
    }
    __syncthreads();

    // L1: 8x8 texels x4
    {
        int c4 = tid & 3, x = (tid >> 2) & 7, y = tid >> 5;
        float4 v = avg4(s0[((2 * y) * 16 + 2 * x) * 4 + c4],
                        s0[((2 * y) * 16 + 2 * x + 1) * 4 + c4],
                        s0[((2 * y + 1) * 16 + 2 * x) * 4 + c4],
                        s0[((2 * y + 1) * 16 + 2 * x + 1) * 4 + c4]);
        s1[tid] = v;
        st_h4(hp + (size_t)(c_off[1] + (ty * 8 + y) * 256 + tx * 8 + x) * 16 + c4 * 4, v);
    }
    __syncthreads();

    // L2: 4x4 x4
    if (tid < 64) {
        int c4 = tid & 3, x = (tid >> 2) & 3, y = tid >> 4;
        float4 v = avg4(s1[((2 * y) * 8 + 2 * x) * 4 + c4],
                        s1[((2 * y) * 8 + 2 * x + 1) * 4 + c4],
                        s1[((2 * y + 1) * 8 + 2 * x) * 4 + c4],
                        s1[((2 * y + 1) * 8 + 2 * x + 1) * 4 + c4]);
        s2[tid] = v;
        st_h4(hp + (size_t)(c_off[2] + (ty * 4 + y) * 128 + tx * 4 + x) * 16 + c4 * 4, v);
    }
    __syncthreads();

    // L3: 2x2 x4
    if (tid < 16) {
        int c4 = tid & 3, x = (tid >> 2) & 1, y = tid >> 3;
        float4 v = avg4(s2[((2 * y) * 4 + 2 * x) * 4 + c4],
                        s2[((2 * y) * 4 + 2 * x + 1) * 4 + c4],
                        s2[((2 * y + 1) * 4 + 2 * x) * 4 + c4],
                        s2[((2 * y + 1) * 4 + 2 * x + 1) * 4 + c4]);
        s3[tid] = v;
        st_h4(hp + (size_t)(c_off[3] + (ty * 2 + y) * 64 + tx * 2 + x) * 16 + c4 * 4, v);
    }
    __syncthreads();

    // L4: one texel per tile
    if (tid < 4) {
        int c4 = tid;
        float4 v = avg4(s3[0 * 4 + c4], s3[1 * 4 + c4], s3[2 * 4 + c4], s3[3 * 4 + c4]);
        st_h4(hp + (size_t)(c_off[4] + ty * 32 + tx) * 16 + c4 * 4, v);
        g_l4[((size_t)plane * 1024 + ty * 32 + tx) * 4 + c4] = v;
    }
}

// ---------------------------------------------------------------------------
// ds_tail: one block per plane, 1024 threads. L5, L6, L7 from fp32 L4.
// ---------------------------------------------------------------------------
__global__ void ds_tail() {
    __shared__ float4 sl5[1024];    // 16x16 x4

    const int plane = blockIdx.x;
    const int tid = threadIdx.x;
    const float4* L4 = g_l4 + (size_t)plane * 1024 * 4;
    __half* hp = g_pyrh + (size_t)plane * PLT * 16;

    // L5: 16x16 x4 = 1024 outputs
    {
        int c4 = tid & 3, x = (tid >> 2) & 15, y = tid >> 6;
        float4 v = avg4(L4[((2 * y) * 32 + 2 * x) * 4 + c4],
                        L4[((2 * y) * 32 + 2 * x + 1) * 4 + c4],
                        L4[((2 * y + 1) * 32 + 2 * x) * 4 + c4],
                        L4[((2 * y + 1) * 32 + 2 * x + 1) * 4 + c4]);
        sl5[tid] = v;
        st_h4(hp + (size_t)(c_off[5] + y * 16 + x) * 16 + c4 * 4, v);
    }
    __syncthreads();

    // L6: 8x8 x4
    if (tid < 256) {
        int c4 = tid & 3, x = (tid >> 2) & 7, y = tid >> 5;
        float4 v = avg4(sl5[((2 * y) * 16 + 2 * x) * 4 + c4],
                        sl5[((2 * y) * 16 + 2 * x + 1) * 4 + c4],
                        sl5[((2 * y + 1) * 16 + 2 * x) * 4 + c4],
                        sl5[((2 * y + 1) * 16 + 2 * x + 1) * 4 + c4]);
        st_h4(hp + (size_t)(c_off[6] + y * 8 + x) * 16 + c4 * 4, v);
    }

    // L7: 4x4 x4 via 4x4 box of L5 (== cascaded 2x2 means)
    if (tid < 64) {
        int c4 = tid & 3, x = (tid >> 2) & 3, y = tid >> 4;
        float4 acc = make_float4(0.f, 0.f, 0.f, 0.f);
        #pragma unroll
        for (int dy = 0; dy < 4; ++dy)
            #pragma unroll
            for (int dx = 0; dx < 4; ++dx) {
                float4 t = sl5[((4 * y + dy) * 16 + 4 * x + dx) * 4 + c4];
                acc.x += t.x; acc.y += t.y; acc.z += t.z; acc.w += t.w;
            }
        float4 v = make_float4(acc.x * 0.0625f, acc.y * 0.0625f,
                               acc.z * 0.0625f, acc.w * 0.0625f);
        st_h4(hp + (size_t)(c_off[7] + y * 4 + x) * 16 + c4 * 4, v);
    }
}

// ---------------------------------------------------------------------------
// Sampling: 4 lanes per (point, plane): lane = (cx, c2).
// L0 taps read fp32 fm directly; levels 1..7 read the fp16 pyramid.
// ---------------------------------------------------------------------------
struct Corn {
    int xa, xb, ya, yb;
    float fx, fy;
};

__device__ __forceinline__ Corn corners(float u, float v, int size) {
    Corn c;
    const float fs = (float)size;
    const float px = u * fs - 0.5f;
    const float py = v * fs - 0.5f;
    const float x0f = floorf(px);
    const float y0f = floorf(py);
    c.fx = px - x0f;
    c.fy = py - y0f;
    const int x0 = (int)x0f;
    const int y0 = (int)y0f;
    const int sm1 = size - 1;
    c.xa = min(max(x0, 0), sm1);
    c.xb = min(max(x0 + 1, 0), sm1);
    c.ya = min(max(y0, 0), sm1);
    c.yb = min(max(y0 + 1, 0), sm1);
    return c;
}

// fp16 tap at level li (>=1), lane handles corner xc (cx) and channel half c2.
__device__ __forceinline__ void tap16(const uint4* __restrict__ pyr, int li,
                                      float u, float v, int cx, int c2,
                                      float wm, float4& A, float4& B) {
    const int size = 512 >> li;
    Corn c = corners(u, v, size);
    const int xc = cx ? c.xb : c.xa;
    const float wx = cx ? c.fx : (1.f - c.fx);

    const uint4* bl = pyr + c_off[li] * 2;
    const uint4 ra = __ldg(bl + (c.ya * size + xc) * 2 + c2);
    const uint4 rb = __ldg(bl + (c.yb * size + xc) * 2 + c2);

    const __half2 wya = __float2half2_rn(1.f - c.fy);
    const __half2 wyb = __float2half2_rn(c.fy);
    const __half2 h0 = __hfma2(*(const __half2*)&rb.x, wyb, __hmul2(*(const __half2*)&ra.x, wya));
    const __half2 h1 = __hfma2(*(const __half2*)&rb.y, wyb, __hmul2(*(const __half2*)&ra.y, wya));
    const __half2 h2 = __hfma2(*(const __half2*)&rb.z, wyb, __hmul2(*(const __half2*)&ra.z, wya));
    const __half2 h3 = __hfma2(*(const __half2*)&rb.w, wyb, __hmul2(*(const __half2*)&ra.w, wya));

    const float wl = wx * wm;
    const float2 f0 = __half22float2(h0);
    const float2 f1 = __half22float2(h1);
    const float2 f2 = __half22float2(h2);
    const float2 f3 = __half22float2(h3);
    A.x = fmaf(wl, f0.x, A.x); A.y = fmaf(wl, f0.y, A.y);
    A.z = fmaf(wl, f1.x, A.z); A.w = fmaf(wl, f1.y, A.w);
    B.x = fmaf(wl, f2.x, B.x); B.y = fmaf(wl, f2.y, B.y);
    B.z = fmaf(wl, f3.x, B.z); B.w = fmaf(wl, f3.y, B.w);
}

// fp32 tap at level 0 straight from fm.
__device__ __forceinline__ void tap32(const float4* __restrict__ fm, int plane,
                                      float u, float v, int cx, int c2,
                                      float wm, float4& A, float4& B) {
    Corn c = corners(u, v, 512);
    const int xc = cx ? c.xb : c.xa;
    const float wx = cx ? c.fx : (1.f - c.fx);

    const float4* base = fm + (size_t)plane * (512 * 512 * 4) + c2 * 2;
    const float4 a0 = __ldg(base + (c.ya * 512 + xc) * 4);
    const float4 a1 = __ldg(base + (c.ya * 512 + xc) * 4 + 1);
    const float4 b0 = __ldg(base + (c.yb * 512 + xc) * 4);
    const float4 b1 = __ldg(base + (c.yb * 512 + xc) * 4 + 1);

    const float wl = wx * wm;
    const float wa = wl * (1.f - c.fy);
    const float wb = wl * c.fy;
    A.x = fmaf(wa, a0.x, fmaf(wb, b0.x, A.x));
    A.y = fmaf(wa, a0.y, fmaf(wb, b0.y, A.y));
    A.z = fmaf(wa, a0.z, fmaf(wb, b0.z, A.z));
    A.w = fmaf(wa, a0.w, fmaf(wb, b0.w, A.w));
    B.x = fmaf(wa, a1.x, fmaf(wb, b1.x, B.x));
    B.y = fmaf(wa, a1.y, fmaf(wb, b1.y, B.y));
    B.z = fmaf(wa, a1.z, fmaf(wb, b1.z, B.z));
    B.w = fmaf(wa, a1.w, fmaf(wb, b1.w, B.w));
}

__global__ void sample_kernel(const float* __restrict__ xin,
                              const float* __restrict__ level,
                              const float4* __restrict__ fm,
                              float4* __restrict__ out, int N3) {
    const int gid = blockIdx.x * blockDim.x + threadIdx.x;
    const int ps = gid >> 2;
    if (ps >= N3) return;
    const int sub = gid & 3;
    const int c2 = sub & 1;
    const int cx = sub >> 1;
    const int pt = ps / 3;
    const int plane = ps - pt * 3;

    const float xv = __ldg(xin + pt * 3 + 0);
    const float yv = __ldg(xin + pt * 3 + 1);
    const float zv = __ldg(xin + pt * 3 + 2);
    const float u = (plane == 0) ? yv : xv;
    const float v = (plane == 2) ? yv : zv;

    float lvl = fminf(fmaxf(__ldg(level + pt), 0.f), 7.f);
    const float l0f = floorf(lvl);
    const float f = lvl - l0f;
    const int l0 = (int)l0f;
    const int l1 = min(l0 + 1, 7);

    const uint4* pyr = reinterpret_cast<const uint4*>(g_pyrh) + (size_t)plane * PLT * 2;

    float4 A = make_float4(0.f, 0.f, 0.f, 0.f);   // channels [c2*8 .. +4)
    float4 B = make_float4(0.f, 0.f, 0.f, 0.f);   // channels [c2*8+4 .. +8)

    if (l0 == 0) tap32(fm, plane, u, v, cx, c2, 1.f - f, A, B);
    else         tap16(pyr, l0, u, v, cx, c2, 1.f - f, A, B);
    tap16(pyr, l1, u, v, cx, c2, f, A, B);

    // reduce over cx (xor lane mask 2)
    const unsigned m = 0xFFFFFFFFu;
    A.x += __shfl_xor_sync(m, A.x, 2);
    A.y += __shfl_xor_sync(m, A.y, 2);
    A.z += __shfl_xor_sync(m, A.z, 2);
    A.w += __shfl_xor_sync(m, A.w, 2);
    B.x += __shfl_xor_sync(m, B.x, 2);
    B.y += __shfl_xor_sync(m, B.y, 2);
    B.z += __shfl_xor_sync(m, B.z, 2);
    B.w += __shfl_xor_sync(m, B.w, 2);

    const float4 o = cx ? B : A;
    out[ps * 4 + c2 * 2 + cx] = o;
}

extern "C" void kernel_launch(void* const* d_in, const int* in_sizes, int n_in,
                              void* d_out, int out_size) {
    const float*  x     = (const float*)d_in[0];
    const float*  level = (const float*)d_in[1];
    const float4* fm    = (const float4*)d_in[2];
    float4* out = (float4*)d_out;
    const int N = in_sizes[0] / 3;
    const int N3 = N * 3;

    ds_fused<<<3 * 1024, 256>>>(fm);
    ds_tail<<<3, 1024>>>();

    const int total = N3 * 4;
    const int threads = 256;
    sample_kernel<<<(total + threads - 1) / threads, threads>>>(x, level, fm, out, N3);
}